// round 13
// baseline (speedup 1.0000x reference)
#include <cuda_runtime.h>
#include <math.h>

#define B_  2
#define S_  2048
#define D_  1024
#define H_  16
#define HD_ 64

typedef unsigned long long ull;

// ---- packed f32x2 helpers (Blackwell sm_103a) ------------------------------
__device__ __forceinline__ ull fma2(ull a, ull b, ull c) {
    ull d; asm("fma.rn.f32x2 %0, %1, %2, %3;" : "=l"(d) : "l"(a), "l"(b), "l"(c));
    return d;
}
__device__ __forceinline__ ull mul2(ull a, ull b) {
    ull d; asm("mul.rn.f32x2 %0, %1, %2;" : "=l"(d) : "l"(a), "l"(b));
    return d;
}
__device__ __forceinline__ ull pack2(float x, float y) {
    ull d; asm("mov.b64 %0, {%1, %2};" : "=l"(d) : "f"(x), "f"(y));
    return d;
}
__device__ __forceinline__ float2 unpack2(ull v) {
    float2 f; asm("mov.b64 {%0, %1}, %2;" : "=f"(f.x), "=f"(f.y) : "l"(v));
    return f;
}

// Scratch (allocation-free rule: device globals)
__device__ float g_q[B_ * S_ * D_];
__device__ float g_k[B_ * S_ * D_];
__device__ float g_v[B_ * S_ * D_];
__device__ float g_att[B_ * S_ * D_];
__device__ float g_cos[S_ * (HD_ / 2)];
__device__ float g_sin[S_ * (HD_ / 2)];

// ---------------------------------------------------------------------------
// RoPE tables (float64 angle math, matching numpy promotion in the reference)
// ---------------------------------------------------------------------------
__global__ void rope_init_kernel() {
    int idx = blockIdx.x * blockDim.x + threadIdx.x;
    if (idx < S_ * 32) {
        int s = idx >> 5, p = idx & 31;
        double inv = pow(10000.0, -((double)(2 * p)) / 64.0);
        double ang = (double)s * inv;
        g_cos[idx] = (float)cos(ang);
        g_sin[idx] = (float)sin(ang);
    }
}

// ---------------------------------------------------------------------------
// SGEMM (NT): C[m,n] = sum_k A[m,k]*W[n,k] + bias[n]
// BM=BN=128, BK=16, 256 threads, 8x8/thread, FFMA2 mainloop.
// A tile stored DUPLICATED in smem so broadcast pairs load directly (no packs).
// mode: 0->C=g_q(+RoPE), 1->C=g_k(+RoPE), 2->C=g_v, 3->A=g_att, C=Cext
// ---------------------------------------------------------------------------
__global__ __launch_bounds__(256, 2) void gemm_kernel(
    const float* __restrict__ Aext, const float* __restrict__ W,
    const float* __restrict__ bias, float* __restrict__ Cext, int mode)
{
    __shared__ float As2[16][264];   // duplicated: As2[kk][2r]=As2[kk][2r+1]=A val
    __shared__ float Bs[16][132];

    const float* A = (mode == 3) ? g_att : Aext;
    float* C = (mode == 0) ? g_q : (mode == 1) ? g_k : (mode == 2) ? g_v : Cext;
    const bool rope = (mode <= 1);

    const int m0 = blockIdx.y * 128;
    const int n0 = blockIdx.x * 128;
    const int tid = threadIdx.x;
    const int tx = tid & 15, ty = tid >> 4;
    const int lrow = tid >> 2;          // 0..63
    const int lk   = (tid & 3) << 2;    // 0,4,8,12

    ull acc2[8][4];                     // rows i=0..7, col-pairs j=0..3
#pragma unroll
    for (int i = 0; i < 8; i++)
#pragma unroll
        for (int j = 0; j < 4; j++) acc2[i][j] = 0ULL;

    for (int k0 = 0; k0 < D_; k0 += 16) {
#pragma unroll
        for (int p = 0; p < 2; p++) {
            const int r = lrow + p * 64;
            float4 av = *(const float4*)(A + (m0 + r) * D_ + k0 + lk);
            *(float2*)&As2[lk + 0][2 * r] = make_float2(av.x, av.x);
            *(float2*)&As2[lk + 1][2 * r] = make_float2(av.y, av.y);
            *(float2*)&As2[lk + 2][2 * r] = make_float2(av.z, av.z);
            *(float2*)&As2[lk + 3][2 * r] = make_float2(av.w, av.w);
            float4 wv = *(const float4*)(W + (n0 + r) * D_ + k0 + lk);
            Bs[lk + 0][r] = wv.x; Bs[lk + 1][r] = wv.y;
            Bs[lk + 2][r] = wv.z; Bs[lk + 3][r] = wv.w;
        }
        __syncthreads();
#pragma unroll
        for (int kk = 0; kk < 16; kk++) {
            // broadcast-packed A: (a,a) pairs straight from duplicated smem
            ulonglong2 aL0 = *(const ulonglong2*)&As2[kk][ty * 8];
            ulonglong2 aL1 = *(const ulonglong2*)&As2[kk][ty * 8 + 4];
            ulonglong2 aH0 = *(const ulonglong2*)&As2[kk][128 + ty * 8];
            ulonglong2 aH1 = *(const ulonglong2*)&As2[kk][128 + ty * 8 + 4];
            // B col pairs: consecutive floats alias as packed pairs
            ulonglong2 b0 = *(const ulonglong2*)&Bs[kk][tx * 4];
            ulonglong2 b1 = *(const ulonglong2*)&Bs[kk][64 + tx * 4];
            const ull a[8] = {aL0.x, aL0.y, aL1.x, aL1.y,
                              aH0.x, aH0.y, aH1.x, aH1.y};
            const ull b[4] = {b0.x, b0.y, b1.x, b1.y};
#pragma unroll
            for (int i = 0; i < 8; i++)
#pragma unroll
                for (int j = 0; j < 4; j++)
                    acc2[i][j] = fma2(a[i], b[j], acc2[i][j]);
        }
        __syncthreads();
    }

    // Epilogue: bias (+ optional RoPE), float4 stores.
#pragma unroll
    for (int rb = 0; rb < 2; rb++)
#pragma unroll
        for (int i = 0; i < 4; i++) {
            const int ai = rb * 4 + i;
            const int m = m0 + rb * 64 + ty * 4 + i;
            const int s = m & (S_ - 1);
#pragma unroll
            for (int cb = 0; cb < 2; cb++) {
                const int n = n0 + cb * 64 + tx * 4;
                float2 f0 = unpack2(acc2[ai][cb * 2 + 0]);
                float2 f1 = unpack2(acc2[ai][cb * 2 + 1]);
                float4 bsv = *(const float4*)(bias + n);
                float4 v;
                v.x = f0.x + bsv.x; v.y = f0.y + bsv.y;
                v.z = f1.x + bsv.z; v.w = f1.y + bsv.w;
                if (rope) {
                    const int p0 = (n & 63) >> 1;
                    const float c0 = g_cos[s * 32 + p0],     s0 = g_sin[s * 32 + p0];
                    const float c1 = g_cos[s * 32 + p0 + 1], s1 = g_sin[s * 32 + p0 + 1];
                    float o0 = v.x * c0 - v.y * s0;
                    float o1 = v.x * s0 + v.y * c0;
                    float o2 = v.z * c1 - v.w * s1;
                    float o3 = v.z * s1 + v.w * c1;
                    v = make_float4(o0, o1, o2, o3);
                }
                *(float4*)(C + m * D_ + n) = v;
            }
        }
}

// ---------------------------------------------------------------------------
// Flash attention, fp32 with FFMA2 inner loops. CTA = (64 rows, head, batch).
// 256 thr (16x16). Qs[d][r] transposed, KPs = K[d][c] then P[r][c], Vs[c][d].
// 48 KB static shared.
// ---------------------------------------------------------------------------
__global__ __launch_bounds__(256) void attn_kernel(const int* __restrict__ eff)
{
    __shared__ float Qs[64 * 64];
    __shared__ float KPs[64 * 64];
    __shared__ float Vs[64 * 64];

    const int m0 = blockIdx.x * 64;
    const int h  = blockIdx.y;
    const int b  = blockIdx.z;
    const int kvlim = S_ - eff[b];

    const int tid = threadIdx.x;
    const int tx = tid & 15, ty = tid >> 4;

    const float* Qg = g_q + b * S_ * D_ + h * 64;
    const float* Kg = g_k + b * S_ * D_ + h * 64;
    const float* Vg = g_v + b * S_ * D_ + h * 64;

#pragma unroll
    for (int it = 0; it < 16; it++) {
        const int idx = tid + it * 256;
        const int r = idx >> 6, d = idx & 63;
        Qs[d * 64 + r] = Qg[(m0 + r) * D_ + d];
    }

    float m_i[4], l_i[4];
    ull O2[4][2];
#pragma unroll
    for (int i = 0; i < 4; i++) {
        m_i[i] = -1e30f; l_i[i] = 0.0f;
        O2[i][0] = 0ULL; O2[i][1] = 0ULL;
    }

    const int nt = min(m0 + 64, kvlim);
    for (int c0 = 0; c0 < nt; c0 += 64) {
        __syncthreads();
#pragma unroll
        for (int it = 0; it < 16; it++) {
            const int idx = tid + it * 256;
            const int c = idx >> 6, d = idx & 63;
            KPs[d * 64 + c] = Kg[(c0 + c) * D_ + d];
            Vs[c * 64 + d]  = Vg[(c0 + c) * D_ + d];
        }
        __syncthreads();

        // S = Q K^T via FFMA2 (k pairs direct from smem, q broadcast-packed)
        ull sc2[4][2];
#pragma unroll
        for (int i = 0; i < 4; i++) { sc2[i][0] = 0ULL; sc2[i][1] = 0ULL; }
#pragma unroll 16
        for (int d = 0; d < 64; d++) {
            const float4 q4 = *(const float4*)&Qs[d * 64 + ty * 4];
            const ulonglong2 k2 = *(const ulonglong2*)&KPs[d * 64 + tx * 4];
            const ull qa[4] = {pack2(q4.x, q4.x), pack2(q4.y, q4.y),
                               pack2(q4.z, q4.z), pack2(q4.w, q4.w)};
#pragma unroll
            for (int i = 0; i < 4; i++) {
                sc2[i][0] = fma2(qa[i], k2.x, sc2[i][0]);
                sc2[i][1] = fma2(qa[i], k2.y, sc2[i][1]);
            }
        }

        // Unpack, scale + causal/pad mask
        float sc[4][4];
#pragma unroll
        for (int i = 0; i < 4; i++) {
            const float2 f0 = unpack2(sc2[i][0]);
            const float2 f1 = unpack2(sc2[i][1]);
            sc[i][0] = f0.x; sc[i][1] = f0.y; sc[i][2] = f1.x; sc[i][3] = f1.y;
            const int r = m0 + ty * 4 + i;
#pragma unroll
            for (int j = 0; j < 4; j++) {
                const int c = c0 + tx * 4 + j;
                sc[i][j] = (c <= r && c < kvlim) ? sc[i][j] * 0.125f : -1e30f;
            }
        }

        // Online softmax (16-lane row groups)
        float p[4][4];
#pragma unroll
        for (int i = 0; i < 4; i++) {
            float rm = fmaxf(fmaxf(sc[i][0], sc[i][1]), fmaxf(sc[i][2], sc[i][3]));
#pragma unroll
            for (int o = 8; o >= 1; o >>= 1)
                rm = fmaxf(rm, __shfl_xor_sync(0xffffffffu, rm, o, 16));
            const float mn = fmaxf(m_i[i], rm);
            const float alpha = __expf(m_i[i] - mn);
            m_i[i] = mn;
            float rs = 0.0f;
#pragma unroll
            for (int j = 0; j < 4; j++) {
                p[i][j] = __expf(sc[i][j] - mn);
                rs += p[i][j];
            }
#pragma unroll
            for (int o = 8; o >= 1; o >>= 1)
                rs += __shfl_xor_sync(0xffffffffu, rs, o, 16);
            l_i[i] = l_i[i] * alpha + rs;
            const ull al = pack2(alpha, alpha);
            O2[i][0] = mul2(O2[i][0], al);
            O2[i][1] = mul2(O2[i][1], al);
        }

        __syncthreads();  // K reads from KPs complete
#pragma unroll
        for (int i = 0; i < 4; i++)
            *(float4*)&KPs[(ty * 4 + i) * 64 + tx * 4] =
                make_float4(p[i][0], p[i][1], p[i][2], p[i][3]);
        __syncthreads();

        // O += P @ V via FFMA2 (v pairs direct, p broadcast-packed, p vec loads)
#pragma unroll 8
        for (int c = 0; c < 64; c += 4) {
            float4 pr[4];
#pragma unroll
            for (int i = 0; i < 4; i++)
                pr[i] = *(const float4*)&KPs[(ty * 4 + i) * 64 + c];
#pragma unroll
            for (int cc = 0; cc < 4; cc++) {
                const ulonglong2 v2 = *(const ulonglong2*)&Vs[(c + cc) * 64 + tx * 4];
#pragma unroll
                for (int i = 0; i < 4; i++) {
                    const float pv = (&pr[i].x)[cc];
                    const ull pp = pack2(pv, pv);
                    O2[i][0] = fma2(pp, v2.x, O2[i][0]);
                    O2[i][1] = fma2(pp, v2.y, O2[i][1]);
                }
            }
        }
    }

    // Normalize + store
#pragma unroll
    for (int i = 0; i < 4; i++) {
        const float inv = 1.0f / l_i[i];
        const float2 f0 = unpack2(O2[i][0]);
        const float2 f1 = unpack2(O2[i][1]);
        const float4 o4 = make_float4(f0.x * inv, f0.y * inv,
                                      f1.x * inv, f1.y * inv);
        *(float4*)&g_att[(b * S_ + m0 + ty * 4 + i) * D_ + h * 64 + tx * 4] = o4;
    }
}

// ---------------------------------------------------------------------------
extern "C" void kernel_launch(void* const* d_in, const int* in_sizes, int n_in,
                              void* d_out, int out_size)
{
    (void)in_sizes; (void)n_in; (void)out_size;
    const float* x  = (const float*)d_in[0];
    const int*   ef = (const int*)  d_in[1];
    const float* Wq = (const float*)d_in[2];
    const float* bq = (const float*)d_in[3];
    const float* Wk = (const float*)d_in[4];
    const float* bk = (const float*)d_in[5];
    const float* Wv = (const float*)d_in[6];
    const float* bv = (const float*)d_in[7];
    const float* Wo = (const float*)d_in[8];
    const float* bo = (const float*)d_in[9];
    float* out = (float*)d_out;

    rope_init_kernel<<<(S_ * 32 + 255) / 256, 256>>>();

    const dim3 gg(D_ / 128, (B_ * S_) / 128);   // 8 x 32
    gemm_kernel<<<gg, 256>>>(x, Wq, bq, nullptr, 0);  // Q + RoPE
    gemm_kernel<<<gg, 256>>>(x, Wk, bk, nullptr, 1);  // K + RoPE
    gemm_kernel<<<gg, 256>>>(x, Wv, bv, nullptr, 2);  // V

    attn_kernel<<<dim3(S_ / 64, H_, B_), 256>>>(ef);

    gemm_kernel<<<gg, 256>>>(nullptr, Wo, bo, out, 3);  // out proj
}